// round 6
// baseline (speedup 1.0000x reference)
#include <cuda_runtime.h>
#include <math.h>

#define NN   50000
#define NE   800000
#define DIN  128
#define DH   256
#define DOUT 16

// ---- static scratch ----
__device__ int   g_deg[NN];
__device__ float g_dinv[NN];
__device__ float g_h1  [(size_t)NN * DH];    // x @ W1
__device__ float g_h1g [(size_t)NN * DH];    // A_hat @ h1
__device__ float g_h1a [(size_t)NN * DH];    // relu(h1g + b1)
__device__ float g_h2  [(size_t)NN * DOUT];  // h1a @ W2
__device__ float g_h2a [(size_t)NN * DOUT];  // A_hat @ h2

// ---------------- degree / norm ----------------

__global__ void k_zero_deg() {
    int i = blockIdx.x * blockDim.x + threadIdx.x;
    if (i < NN) g_deg[i] = 0;
}

__global__ void k_count(const int* __restrict__ ei, int E) {
    int e = blockIdx.x * blockDim.x + threadIdx.x;
    if (e < E) {
        int d = ei[E + e];
        if ((unsigned)d < (unsigned)NN) atomicAdd(&g_deg[d], 1);
    }
}

__global__ void k_dinv() {
    int i = blockIdx.x * blockDim.x + threadIdx.x;
    if (i < NN) g_dinv[i] = rsqrtf((float)(g_deg[i] + 1));
}

// ---------------- naive GEMM1: h1 = x @ W1  (one thread per output) ----------------

__global__ void k_gemm1n(const float* __restrict__ x, const float* __restrict__ W1) {
    int id = blockIdx.x * blockDim.x + threadIdx.x;       // NN*DH
    if (id >= NN * DH) return;
    int r = id / DH, c = id % DH;
    const float* xr = x + (size_t)r * DIN;
    float acc = 0.f;
    for (int k = 0; k < DIN; k++) acc += xr[k] * W1[k * DH + c];
    g_h1[id] = acc;
}

// ---------------- layer-1 aggregation (transform-first, exact reference order) ----------------

__global__ void k_self1() {
    int id = blockIdx.x * blockDim.x + threadIdx.x;       // NN*DH
    if (id >= NN * DH) return;
    int i = id / DH;
    float di = g_dinv[i];
    g_h1g[id] = g_h1[id] * di * di;
}

// one warp per edge, 256 features = 2 float4 per lane
__global__ __launch_bounds__(256) void k_edge1(const int* __restrict__ ei, int E) {
    int w    = (blockIdx.x * blockDim.x + threadIdx.x) >> 5;
    int lane = threadIdx.x & 31;
    if (w >= E) return;
    int s = ei[w], d = ei[E + w];
    if ((unsigned)s >= (unsigned)NN || (unsigned)d >= (unsigned)NN) return;
    float wt = g_dinv[s] * g_dinv[d];
    const float4* sp = (const float4*)(g_h1 + (size_t)s * DH);
    float* dp = g_h1g + (size_t)d * DH;
    #pragma unroll
    for (int h = 0; h < 2; h++) {
        int q = lane + 32 * h;
        float4 v = sp[q];
        atomicAdd(dp + q * 4 + 0, v.x * wt);
        atomicAdd(dp + q * 4 + 1, v.y * wt);
        atomicAdd(dp + q * 4 + 2, v.z * wt);
        atomicAdd(dp + q * 4 + 3, v.w * wt);
    }
}

__global__ void k_birelu(const float* __restrict__ b1) {
    int id = blockIdx.x * blockDim.x + threadIdx.x;       // NN*DH
    if (id >= NN * DH) return;
    g_h1a[id] = fmaxf(g_h1g[id] + b1[id % DH], 0.f);
}

// ---------------- naive GEMM2: h2 = h1a @ W2 ----------------

__global__ void k_gemm2n(const float* __restrict__ W2) {
    int id = blockIdx.x * blockDim.x + threadIdx.x;       // NN*DOUT
    if (id >= NN * DOUT) return;
    int r = id / DOUT, c = id % DOUT;
    const float* a = g_h1a + (size_t)r * DH;
    float acc = 0.f;
    for (int k = 0; k < DH; k++) acc += a[k] * W2[k * DOUT + c];
    g_h2[id] = acc;
}

// ---------------- layer-2 aggregation ----------------

__global__ void k_self2() {
    int id = blockIdx.x * blockDim.x + threadIdx.x;       // NN*DOUT
    if (id >= NN * DOUT) return;
    int i = id / DOUT;
    float di = g_dinv[i];
    g_h2a[id] = g_h2[id] * di * di;
}

__global__ void k_edge2(const int* __restrict__ ei, int E) {
    int t = blockIdx.x * blockDim.x + threadIdx.x;
    int e = t >> 4, l = t & 15;
    if (e >= E) return;
    int s = ei[e], d = ei[E + e];
    if ((unsigned)s >= (unsigned)NN || (unsigned)d >= (unsigned)NN) return;
    float wt = g_dinv[s] * g_dinv[d];
    atomicAdd(&g_h2a[(size_t)d * DOUT + l], g_h2[(size_t)s * DOUT + l] * wt);
}

// ---------------- bias + log_softmax: one thread per node, fully serial ----------------

__global__ void k_out(const float* __restrict__ b2, float* __restrict__ out) {
    int i = blockIdx.x * blockDim.x + threadIdx.x;
    if (i >= NN) return;
    float v[DOUT];
    float m = -1e30f;
    for (int c = 0; c < DOUT; c++) {
        v[c] = g_h2a[(size_t)i * DOUT + c] + b2[c];
        m = fmaxf(m, v[c]);
    }
    float ssum = 0.f;
    for (int c = 0; c < DOUT; c++) ssum += expf(v[c] - m);
    float lse = m + logf(ssum);
    for (int c = 0; c < DOUT; c++) out[(size_t)i * DOUT + c] = v[c] - lse;
}

// ---------------- launch ----------------

extern "C" void kernel_launch(void* const* d_in, const int* in_sizes, int n_in,
                              void* d_out, int out_size) {
    // resolve inputs BY SIZE (all element counts are distinct) — immune to ordering
    const float *x = 0, *W1 = 0, *b1 = 0, *W2 = 0, *b2 = 0;
    const int* ei = 0;
    int E = NE;
    for (int i = 0; i < n_in; i++) {
        int c = in_sizes[i];
        if      (c == NN * DIN)  x  = (const float*)d_in[i];
        else if (c == 2 * NE)  { ei = (const int*)d_in[i]; E = NE; }
        else if (c == DIN * DH)  W1 = (const float*)d_in[i];
        else if (c == DH)        b1 = (const float*)d_in[i];
        else if (c == DH * DOUT) W2 = (const float*)d_in[i];
        else if (c == DOUT)      b2 = (const float*)d_in[i];
    }
    // positional fallback (should not trigger)
    if (!x)  x  = (const float*)d_in[0];
    if (!ei) { ei = (const int*)d_in[1]; E = in_sizes[1] / 2; }
    if (!W1) W1 = (const float*)d_in[2];
    if (!b1) b1 = (const float*)d_in[3];
    if (!W2) W2 = (const float*)d_in[4];
    if (!b2) b2 = (const float*)d_in[5];
    float* out = (float*)d_out;

    // degree / normalization
    k_zero_deg<<<(NN + 255) / 256, 256>>>();
    k_count<<<(E + 255) / 256, 256>>>(ei, E);
    k_dinv<<<(NN + 255) / 256, 256>>>();

    // layer 1 (exact reference order: transform, aggregate, bias, relu)
    k_gemm1n<<<(NN * DH + 255) / 256, 256>>>(x, W1);
    k_self1<<<(NN * DH + 255) / 256, 256>>>();
    k_edge1<<<((size_t)E * 32 + 255) / 256, 256>>>(ei, E);
    k_birelu<<<(NN * DH + 255) / 256, 256>>>(b1);

    // layer 2
    k_gemm2n<<<(NN * DOUT + 255) / 256, 256>>>(W2);
    k_self2<<<(NN * DOUT + 255) / 256, 256>>>();
    k_edge2<<<((size_t)E * 16 + 255) / 256, 256>>>(ei, E);
    k_out<<<(NN + 255) / 256, 256>>>(b2, out);
}

// round 12
// speedup vs baseline: 2.2092x; 2.2092x over previous
#include <cuda_runtime.h>
#include <math.h>

#define NN   50000
#define NE   800000
#define DIN  128
#define DH   256
#define DOUT 16

// ---- static scratch: ONLY referenced from device code (never as host-side kernel args) ----
__device__ int   g_deg[NN];
__device__ float g_dinv[NN];
__device__ float g_xa [(size_t)NN * DIN];    // A_hat @ x
__device__ float g_h1a[(size_t)NN * DH];     // relu((A_hat x) W1 + b1)
__device__ float g_h2 [(size_t)NN * DOUT];   // h1a @ W2
__device__ float g_h2a[(size_t)NN * DOUT];   // A_hat @ h2

// ---------------- degree / norm ----------------

__global__ void k_zero_deg() {
    int i = blockIdx.x * blockDim.x + threadIdx.x;
    if (i < NN) g_deg[i] = 0;
}

__global__ void k_count(const int* __restrict__ ei, int E) {
    int e = blockIdx.x * blockDim.x + threadIdx.x;
    if (e < E) {
        int d = ei[E + e];
        if ((unsigned)d < (unsigned)NN) atomicAdd(&g_deg[d], 1);
    }
}

__global__ void k_dinv() {
    int i = blockIdx.x * blockDim.x + threadIdx.x;
    if (i < NN) g_dinv[i] = rsqrtf((float)(g_deg[i] + 1));
}

// ---------------- layer-1 aggregation on x (aggregate-first; exact by linearity) ----------------

__global__ void k_init_xa(const float* __restrict__ x) {
    int idx = blockIdx.x * blockDim.x + threadIdx.x;   // NN*DIN
    if (idx < NN * DIN) {
        int i = idx / DIN;
        float di = g_dinv[i];
        g_xa[idx] = x[idx] * di * di;
    }
}

// one warp per edge; lane handles one float4 (128 feats = 32 lanes * 4)
__global__ __launch_bounds__(256) void k_edge_x(const float* __restrict__ x,
                                                const int* __restrict__ ei, int E) {
    int w    = (blockIdx.x * blockDim.x + threadIdx.x) >> 5;
    int lane = threadIdx.x & 31;
    if (w >= E) return;
    int s = ei[w], d = ei[E + w];
    if ((unsigned)s >= (unsigned)NN || (unsigned)d >= (unsigned)NN) return;
    float wt = g_dinv[s] * g_dinv[d];
    float4 v = ((const float4*)(x + (size_t)s * DIN))[lane];
    float* dst = g_xa + (size_t)d * DIN + lane * 4;
    atomicAdd(dst + 0, v.x * wt);
    atomicAdd(dst + 1, v.y * wt);
    atomicAdd(dst + 2, v.z * wt);
    atomicAdd(dst + 3, v.w * wt);
}

// ---------------- GEMM1 (tiled, fused bias+relu): g_h1a = relu(g_xa @ W1 + b1) ----------------
// BM=128 BN=64 BK=16, 256 threads, 8x4 outputs/thread. Globals referenced in-device.

__global__ __launch_bounds__(256) void k_gemm1t(const float* __restrict__ B,
                                                const float* __restrict__ bias) {
    __shared__ float As[16][132];   // [k][m], padded
    __shared__ float Bs[16][64];    // [k][n]
    const int tid = threadIdx.x;
    const int tr  = tid >> 4;       // 0..15 -> rows tr*8..tr*8+7
    const int tc  = tid & 15;       // 0..15 -> cols tc*4..tc*4+3
    const int m0  = blockIdx.x * 128;
    const int n0  = blockIdx.y * 64;

    float acc[8][4];
    #pragma unroll
    for (int i = 0; i < 8; i++)
        #pragma unroll
        for (int j = 0; j < 4; j++) acc[i][j] = 0.f;

    for (int k0 = 0; k0 < DIN; k0 += 16) {
        #pragma unroll
        for (int l = 0; l < 8; l++) {
            int idx = tid + l * 256;          // 0..2047
            int m = idx >> 4, kk = idx & 15;
            int gm = m0 + m;
            As[kk][m] = (gm < NN) ? g_xa[(size_t)gm * DIN + k0 + kk] : 0.f;
        }
        #pragma unroll
        for (int l = 0; l < 4; l++) {
            int idx = tid + l * 256;          // 0..1023
            int kk = idx >> 6, n = idx & 63;
            Bs[kk][n] = B[(size_t)(k0 + kk) * DH + n0 + n];
        }
        __syncthreads();
        #pragma unroll
        for (int kk = 0; kk < 16; kk++) {
            float a[8], b[4];
            #pragma unroll
            for (int i = 0; i < 8; i++) a[i] = As[kk][tr * 8 + i];
            #pragma unroll
            for (int j = 0; j < 4; j++) b[j] = Bs[kk][tc * 4 + j];
            #pragma unroll
            for (int i = 0; i < 8; i++)
                #pragma unroll
                for (int j = 0; j < 4; j++)
                    acc[i][j] = fmaf(a[i], b[j], acc[i][j]);
        }
        __syncthreads();
    }

    float4 bb = *(const float4*)(bias + n0 + tc * 4);
    #pragma unroll
    for (int i = 0; i < 8; i++) {
        int gm = m0 + tr * 8 + i;
        if (gm < NN) {
            float4 v;
            v.x = fmaxf(acc[i][0] + bb.x, 0.f);
            v.y = fmaxf(acc[i][1] + bb.y, 0.f);
            v.z = fmaxf(acc[i][2] + bb.z, 0.f);
            v.w = fmaxf(acc[i][3] + bb.w, 0.f);
            *(float4*)&g_h1a[(size_t)gm * DH + n0 + tc * 4] = v;
        }
    }
}

// ---------------- naive GEMM2 (R6 verbatim): g_h2 = g_h1a @ W2 ----------------

__global__ void k_gemm2n(const float* __restrict__ W2) {
    int id = blockIdx.x * blockDim.x + threadIdx.x;       // NN*DOUT
    if (id >= NN * DOUT) return;
    int r = id / DOUT, c = id % DOUT;
    const float* a = g_h1a + (size_t)r * DH;
    float acc = 0.f;
    for (int k = 0; k < DH; k++) acc += a[k] * W2[k * DOUT + c];
    g_h2[id] = acc;
}

// ---------------- layer-2 aggregation (R6 verbatim) ----------------

__global__ void k_self2() {
    int id = blockIdx.x * blockDim.x + threadIdx.x;       // NN*DOUT
    if (id >= NN * DOUT) return;
    int i = id / DOUT;
    float di = g_dinv[i];
    g_h2a[id] = g_h2[id] * di * di;
}

__global__ void k_edge2(const int* __restrict__ ei, int E) {
    int t = blockIdx.x * blockDim.x + threadIdx.x;
    int e = t >> 4, l = t & 15;
    if (e >= E) return;
    int s = ei[e], d = ei[E + e];
    if ((unsigned)s >= (unsigned)NN || (unsigned)d >= (unsigned)NN) return;
    float wt = g_dinv[s] * g_dinv[d];
    atomicAdd(&g_h2a[(size_t)d * DOUT + l], g_h2[(size_t)s * DOUT + l] * wt);
}

// ---------------- bias + log_softmax (R6 verbatim) ----------------

__global__ void k_out(const float* __restrict__ b2, float* __restrict__ out) {
    int i = blockIdx.x * blockDim.x + threadIdx.x;
    if (i >= NN) return;
    float v[DOUT];
    float m = -1e30f;
    for (int c = 0; c < DOUT; c++) {
        v[c] = g_h2a[(size_t)i * DOUT + c] + b2[c];
        m = fmaxf(m, v[c]);
    }
    float ssum = 0.f;
    for (int c = 0; c < DOUT; c++) ssum += expf(v[c] - m);
    float lse = m + logf(ssum);
    for (int c = 0; c < DOUT; c++) out[(size_t)i * DOUT + c] = v[c] - lse;
}

// ---------------- launch ----------------

extern "C" void kernel_launch(void* const* d_in, const int* in_sizes, int n_in,
                              void* d_out, int out_size) {
    // resolve inputs by element count (all distinct)
    const float *x = 0, *W1 = 0, *b1 = 0, *W2 = 0, *b2 = 0;
    const int* ei = 0;
    int E = NE;
    for (int i = 0; i < n_in; i++) {
        int c = in_sizes[i];
        if      (c == NN * DIN)  x  = (const float*)d_in[i];
        else if (c == 2 * NE)  { ei = (const int*)d_in[i]; E = NE; }
        else if (c == DIN * DH)  W1 = (const float*)d_in[i];
        else if (c == DH)        b1 = (const float*)d_in[i];
        else if (c == DH * DOUT) W2 = (const float*)d_in[i];
        else if (c == DOUT)      b2 = (const float*)d_in[i];
    }
    if (!x)  x  = (const float*)d_in[0];
    if (!ei) { ei = (const int*)d_in[1]; E = in_sizes[1] / 2; }
    if (!W1) W1 = (const float*)d_in[2];
    if (!b1) b1 = (const float*)d_in[3];
    if (!W2) W2 = (const float*)d_in[4];
    if (!b2) b2 = (const float*)d_in[5];
    float* out = (float*)d_out;

    // degree / normalization
    k_zero_deg<<<(NN + 255) / 256, 256>>>();
    k_count<<<(E + 255) / 256, 256>>>(ei, E);
    k_dinv<<<(NN + 255) / 256, 256>>>();

    // layer 1: aggregate-first (exact by linearity), then fused tiled GEMM+bias+relu
    k_init_xa<<<(NN * DIN + 255) / 256, 256>>>(x);
    k_edge_x<<<((size_t)E * 32 + 255) / 256, 256>>>(x, ei, E);
    dim3 g1((NN + 127) / 128, DH / 64);
    k_gemm1t<<<g1, 256>>>(W1, b1);

    // layer 2: transform-first, then aggregate, then softmax
    k_gemm2n<<<(NN * DOUT + 255) / 256, 256>>>(W2);
    k_self2<<<(NN * DOUT + 255) / 256, 256>>>();
    k_edge2<<<((size_t)E * 16 + 255) / 256, 256>>>(ei, E);
    k_out<<<(NN + 255) / 256, 256>>>(b2, out);
}

// round 13
// speedup vs baseline: 3.2509x; 1.4715x over previous
#include <cuda_runtime.h>
#include <math.h>

#define NN   50000
#define NE   800000
#define DIN  128
#define DH   256
#define DOUT 16

// ---- static scratch: ONLY referenced from device code ----
__device__ int   g_deg[NN];
__device__ int   g_rowoff[NN + 1];
__device__ int   g_cursor[NN];
__device__ int   g_src[NE];
__device__ float g_dinv[NN];
__device__ float g_xa [(size_t)NN * DIN];    // A_hat @ x
__device__ float g_h1a[(size_t)NN * DH];     // relu((A_hat x) W1 + b1)
__device__ float g_h2 [(size_t)NN * DOUT];   // h1a @ W2

// ---------------- graph build ----------------

__global__ void k_zero_deg() {
    int i = blockIdx.x * blockDim.x + threadIdx.x;
    if (i < NN) g_deg[i] = 0;
}

__global__ void k_count(const int* __restrict__ ei, int E) {
    int e = blockIdx.x * blockDim.x + threadIdx.x;
    if (e < E) {
        int d = ei[E + e];
        if ((unsigned)d < (unsigned)NN) atomicAdd(&g_deg[d], 1);
    }
}

// single-block exclusive scan of g_deg -> g_rowoff, g_cursor
__global__ void k_scan() {
    __shared__ int sh[1024];
    __shared__ int carry;
    int tid = threadIdx.x;
    if (tid == 0) carry = 0;
    __syncthreads();
    for (int base = 0; base < NN; base += 1024) {
        int i = base + tid;
        int v = (i < NN) ? g_deg[i] : 0;
        sh[tid] = v;
        __syncthreads();
        #pragma unroll
        for (int off = 1; off < 1024; off <<= 1) {
            int t = (tid >= off) ? sh[tid - off] : 0;
            __syncthreads();
            sh[tid] += t;
            __syncthreads();
        }
        int c = carry;
        if (i < NN) {
            int excl = c + sh[tid] - v;
            g_rowoff[i] = excl;
            g_cursor[i] = excl;
        }
        __syncthreads();                 // all threads read carry before update
        if (tid == 1023) carry = c + sh[1023];
        __syncthreads();
    }
    if (tid == 0) g_rowoff[NN] = carry;
}

__global__ void k_dinv() {
    int i = blockIdx.x * blockDim.x + threadIdx.x;
    if (i < NN) g_dinv[i] = rsqrtf((float)(g_deg[i] + 1));  // +1 self loop
}

__global__ void k_scatter(const int* __restrict__ ei, int E) {
    int e = blockIdx.x * blockDim.x + threadIdx.x;
    if (e < E) {
        int s = ei[e], d = ei[E + e];
        if ((unsigned)s < (unsigned)NN && (unsigned)d < (unsigned)NN) {
            int pos = atomicAdd(&g_cursor[d], 1);
            g_src[pos] = s;
        }
    }
}

// ---------------- layer-1 aggregation: warp-per-node CSR gather (no atomics) ----------------
// xa[i] = di^2 x[i] + sum_e dinv[s] di x[s]; lane owns one float4 (128 feats)

__global__ __launch_bounds__(256) void k_agg1(const float* __restrict__ x) {
    int i    = (blockIdx.x * 256 + threadIdx.x) >> 5;
    int lane = threadIdx.x & 31;
    if (i >= NN) return;
    float di = g_dinv[i];
    float4 v = ((const float4*)(x + (size_t)i * DIN))[lane];
    float ws = di * di;
    float4 acc = make_float4(v.x * ws, v.y * ws, v.z * ws, v.w * ws);

    int e = g_rowoff[i], end = g_rowoff[i + 1];
    for (; e + 2 <= end; e += 2) {
        int s0 = g_src[e], s1 = g_src[e + 1];
        float w0 = g_dinv[s0] * di, w1 = g_dinv[s1] * di;
        float4 a = ((const float4*)(x + (size_t)s0 * DIN))[lane];
        float4 b = ((const float4*)(x + (size_t)s1 * DIN))[lane];
        acc.x += a.x * w0 + b.x * w1;
        acc.y += a.y * w0 + b.y * w1;
        acc.z += a.z * w0 + b.z * w1;
        acc.w += a.w * w0 + b.w * w1;
    }
    if (e < end) {
        int s = g_src[e];
        float w = g_dinv[s] * di;
        float4 a = ((const float4*)(x + (size_t)s * DIN))[lane];
        acc.x += a.x * w; acc.y += a.y * w; acc.z += a.z * w; acc.w += a.w * w;
    }
    ((float4*)g_xa)[(size_t)i * 32 + lane] = acc;
}

// ---------------- GEMM1 (tiled, fused bias+relu): g_h1a = relu(g_xa @ W1 + b1) ----------------

__global__ __launch_bounds__(256) void k_gemm1t(const float* __restrict__ B,
                                                const float* __restrict__ bias) {
    __shared__ float As[16][132];
    __shared__ float Bs[16][64];
    const int tid = threadIdx.x;
    const int tr  = tid >> 4;
    const int tc  = tid & 15;
    const int m0  = blockIdx.x * 128;
    const int n0  = blockIdx.y * 64;

    float acc[8][4];
    #pragma unroll
    for (int i = 0; i < 8; i++)
        #pragma unroll
        for (int j = 0; j < 4; j++) acc[i][j] = 0.f;

    for (int k0 = 0; k0 < DIN; k0 += 16) {
        #pragma unroll
        for (int l = 0; l < 8; l++) {
            int idx = tid + l * 256;
            int m = idx >> 4, kk = idx & 15;
            int gm = m0 + m;
            As[kk][m] = (gm < NN) ? g_xa[(size_t)gm * DIN + k0 + kk] : 0.f;
        }
        #pragma unroll
        for (int l = 0; l < 4; l++) {
            int idx = tid + l * 256;
            int kk = idx >> 6, n = idx & 63;
            Bs[kk][n] = B[(size_t)(k0 + kk) * DH + n0 + n];
        }
        __syncthreads();
        #pragma unroll
        for (int kk = 0; kk < 16; kk++) {
            float a[8], b[4];
            #pragma unroll
            for (int i = 0; i < 8; i++) a[i] = As[kk][tr * 8 + i];
            #pragma unroll
            for (int j = 0; j < 4; j++) b[j] = Bs[kk][tc * 4 + j];
            #pragma unroll
            for (int i = 0; i < 8; i++)
                #pragma unroll
                for (int j = 0; j < 4; j++)
                    acc[i][j] = fmaf(a[i], b[j], acc[i][j]);
        }
        __syncthreads();
    }

    float4 bb = *(const float4*)(bias + n0 + tc * 4);
    #pragma unroll
    for (int i = 0; i < 8; i++) {
        int gm = m0 + tr * 8 + i;
        if (gm < NN) {
            float4 v;
            v.x = fmaxf(acc[i][0] + bb.x, 0.f);
            v.y = fmaxf(acc[i][1] + bb.y, 0.f);
            v.z = fmaxf(acc[i][2] + bb.z, 0.f);
            v.w = fmaxf(acc[i][3] + bb.w, 0.f);
            *(float4*)&g_h1a[(size_t)gm * DH + n0 + tc * 4] = v;
        }
    }
}

// ---------------- naive GEMM2: g_h2 = g_h1a @ W2 ----------------

__global__ void k_gemm2n(const float* __restrict__ W2) {
    int id = blockIdx.x * blockDim.x + threadIdx.x;       // NN*DOUT
    if (id >= NN * DOUT) return;
    int r = id / DOUT, c = id % DOUT;
    const float* a = g_h1a + (size_t)r * DH;
    float acc = 0.f;
    for (int k = 0; k < DH; k++) acc += a[k] * W2[k * DOUT + c];
    g_h2[id] = acc;
}

// ---------------- layer-2: fused CSR gather + bias + log_softmax ----------------
// 16 lanes per node (one feature each), 16 nodes per 256-thread block

__global__ __launch_bounds__(256) void k_l2fused(const float* __restrict__ b2,
                                                 float* __restrict__ out) {
    int tid  = threadIdx.x;
    int grp  = tid >> 4, lane = tid & 15;
    int i    = blockIdx.x * 16 + grp;
    if (i >= NN) return;
    float di = g_dinv[i];
    float acc = g_h2[(size_t)i * DOUT + lane] * di * di;

    int e = g_rowoff[i], end = g_rowoff[i + 1];
    for (; e + 2 <= end; e += 2) {
        int s0 = g_src[e], s1 = g_src[e + 1];
        float w0 = g_dinv[s0] * di, w1 = g_dinv[s1] * di;
        acc += g_h2[(size_t)s0 * DOUT + lane] * w0
             + g_h2[(size_t)s1 * DOUT + lane] * w1;
    }
    if (e < end) {
        int s = g_src[e];
        acc += g_h2[(size_t)s * DOUT + lane] * (g_dinv[s] * di);
    }
    acc += b2[lane];

    float m = acc;
    #pragma unroll
    for (int off = 8; off; off >>= 1)
        m = fmaxf(m, __shfl_xor_sync(0xffffffffu, m, off, 16));
    float ssum = expf(acc - m);
    #pragma unroll
    for (int off = 8; off; off >>= 1)
        ssum += __shfl_xor_sync(0xffffffffu, ssum, off, 16);
    out[(size_t)i * DOUT + lane] = acc - m - logf(ssum);
}

// ---------------- launch ----------------

extern "C" void kernel_launch(void* const* d_in, const int* in_sizes, int n_in,
                              void* d_out, int out_size) {
    const float *x = 0, *W1 = 0, *b1 = 0, *W2 = 0, *b2 = 0;
    const int* ei = 0;
    int E = NE;
    for (int i = 0; i < n_in; i++) {
        int c = in_sizes[i];
        if      (c == NN * DIN)  x  = (const float*)d_in[i];
        else if (c == 2 * NE)  { ei = (const int*)d_in[i]; E = NE; }
        else if (c == DIN * DH)  W1 = (const float*)d_in[i];
        else if (c == DH)        b1 = (const float*)d_in[i];
        else if (c == DH * DOUT) W2 = (const float*)d_in[i];
        else if (c == DOUT)      b2 = (const float*)d_in[i];
    }
    if (!x)  x  = (const float*)d_in[0];
    if (!ei) { ei = (const int*)d_in[1]; E = in_sizes[1] / 2; }
    if (!W1) W1 = (const float*)d_in[2];
    if (!b1) b1 = (const float*)d_in[3];
    if (!W2) W2 = (const float*)d_in[4];
    if (!b2) b2 = (const float*)d_in[5];
    float* out = (float*)d_out;

    // graph build (CSR by destination)
    k_zero_deg<<<(NN + 255) / 256, 256>>>();
    k_count<<<(E + 255) / 256, 256>>>(ei, E);
    k_scan<<<1, 1024>>>();
    k_dinv<<<(NN + 255) / 256, 256>>>();
    k_scatter<<<(E + 255) / 256, 256>>>(ei, E);

    // layer 1: CSR gather aggregation (exact by linearity), then fused GEMM+bias+relu
    k_agg1<<<(NN * 32 + 255) / 256, 256>>>(x);
    dim3 g1((NN + 127) / 128, DH / 64);
    k_gemm1t<<<g1, 256>>>(W1, b1);

    // layer 2: transform, then fused gather + bias + log_softmax
    k_gemm2n<<<(NN * DOUT + 255) / 256, 256>>>(W2);
    k_l2fused<<<(NN + 15) / 16, 256>>>(b2, out);
}

// round 14
// speedup vs baseline: 4.4221x; 1.3602x over previous
#include <cuda_runtime.h>
#include <math.h>

#define NN   50000
#define NE   800000
#define DIN  128
#define DH   256
#define DOUT 16
#define NBLK ((NN + 1023) / 1024)   // 49 scan blocks

// ---- static scratch: ONLY referenced from device code ----
__device__ int   g_deg[NN];
__device__ int   g_loc[NN];          // per-block exclusive scan
__device__ int   g_bsum[NBLK];
__device__ int   g_boff[NBLK];
__device__ int   g_rowoff[NN + 1];
__device__ int   g_cursor[NN];
__device__ int   g_src[NE];
__device__ float g_dinv[NN];
__device__ float g_xa [(size_t)NN * DIN];    // A_hat @ x
__device__ float g_h1a[(size_t)NN * DH];     // relu((A_hat x) W1 + b1)
__device__ float g_h2 [(size_t)NN * DOUT];   // h1a @ W2

// ---------------- graph build ----------------

__global__ void k_zero_deg() {
    int i = blockIdx.x * blockDim.x + threadIdx.x;
    if (i < NN) g_deg[i] = 0;
}

__global__ void k_count(const int* __restrict__ ei, int E) {
    int e = blockIdx.x * blockDim.x + threadIdx.x;
    if (e < E) {
        int d = ei[E + e];
        if ((unsigned)d < (unsigned)NN) atomicAdd(&g_deg[d], 1);
    }
}

// phase 1: each block scans 1024 degrees -> g_loc (exclusive), g_bsum
__global__ __launch_bounds__(1024) void k_scan1() {
    __shared__ int sh[1024];
    int tid = threadIdx.x;
    int i = blockIdx.x * 1024 + tid;
    int v = (i < NN) ? g_deg[i] : 0;
    sh[tid] = v;
    __syncthreads();
    #pragma unroll
    for (int off = 1; off < 1024; off <<= 1) {
        int t = (tid >= off) ? sh[tid - off] : 0;
        __syncthreads();
        sh[tid] += t;
        __syncthreads();
    }
    if (i < NN) g_loc[i] = sh[tid] - v;
    if (tid == 1023) g_bsum[blockIdx.x] = sh[1023];
}

// phase 2: one warp scans the NBLK partials -> g_boff (exclusive), total
__global__ void k_scan2() {
    int tid = threadIdx.x;          // 64 threads
    __shared__ int sh[64];
    int v = (tid < NBLK) ? g_bsum[tid] : 0;
    sh[tid] = v;
    __syncthreads();
    #pragma unroll
    for (int off = 1; off < 64; off <<= 1) {
        int t = (tid >= off) ? sh[tid - off] : 0;
        __syncthreads();
        sh[tid] += t;
        __syncthreads();
    }
    if (tid < NBLK) g_boff[tid] = sh[tid] - v;
    if (tid == 63) g_rowoff[NN] = sh[63];
}

// phase 3: apply offsets + dinv
__global__ void k_scan3() {
    int i = blockIdx.x * blockDim.x + threadIdx.x;
    if (i < NN) {
        int o = g_loc[i] + g_boff[i >> 10];
        g_rowoff[i] = o;
        g_cursor[i] = o;
        g_dinv[i]   = rsqrtf((float)(g_deg[i] + 1));  // +1 self loop
    }
}

__global__ void k_scatter(const int* __restrict__ ei, int E) {
    int e = blockIdx.x * blockDim.x + threadIdx.x;
    if (e < E) {
        int s = ei[e], d = ei[E + e];
        if ((unsigned)s < (unsigned)NN && (unsigned)d < (unsigned)NN) {
            int pos = atomicAdd(&g_cursor[d], 1);
            g_src[pos] = s;
        }
    }
}

// ---------------- layer-1 aggregation: warp-per-node CSR gather, 4-way unrolled ----------------

__global__ __launch_bounds__(256) void k_agg1(const float* __restrict__ x) {
    int i    = (blockIdx.x * 256 + threadIdx.x) >> 5;
    int lane = threadIdx.x & 31;
    if (i >= NN) return;
    float di = g_dinv[i];
    float4 v = ((const float4*)(x + (size_t)i * DIN))[lane];
    float ws = di * di;
    float4 acc = make_float4(v.x * ws, v.y * ws, v.z * ws, v.w * ws);

    int e = g_rowoff[i], end = g_rowoff[i + 1];
    for (; e + 4 <= end; e += 4) {
        int s0 = g_src[e],     s1 = g_src[e + 1];
        int s2 = g_src[e + 2], s3 = g_src[e + 3];
        float w0 = g_dinv[s0] * di, w1 = g_dinv[s1] * di;
        float w2 = g_dinv[s2] * di, w3 = g_dinv[s3] * di;
        float4 a = ((const float4*)(x + (size_t)s0 * DIN))[lane];
        float4 b = ((const float4*)(x + (size_t)s1 * DIN))[lane];
        float4 c = ((const float4*)(x + (size_t)s2 * DIN))[lane];
        float4 d = ((const float4*)(x + (size_t)s3 * DIN))[lane];
        acc.x += a.x * w0 + b.x * w1 + c.x * w2 + d.x * w3;
        acc.y += a.y * w0 + b.y * w1 + c.y * w2 + d.y * w3;
        acc.z += a.z * w0 + b.z * w1 + c.z * w2 + d.z * w3;
        acc.w += a.w * w0 + b.w * w1 + c.w * w2 + d.w * w3;
    }
    for (; e < end; e++) {
        int s = g_src[e];
        float w = g_dinv[s] * di;
        float4 a = ((const float4*)(x + (size_t)s * DIN))[lane];
        acc.x += a.x * w; acc.y += a.y * w; acc.z += a.z * w; acc.w += a.w * w;
    }
    ((float4*)g_xa)[(size_t)i * 32 + lane] = acc;
}

// ---------------- GEMM1 (tiled, fused bias+relu): g_h1a = relu(g_xa @ W1 + b1) ----------------

__global__ __launch_bounds__(256) void k_gemm1t(const float* __restrict__ B,
                                                const float* __restrict__ bias) {
    __shared__ float As[16][132];
    __shared__ float Bs[16][64];
    const int tid = threadIdx.x;
    const int tr  = tid >> 4;
    const int tc  = tid & 15;
    const int m0  = blockIdx.x * 128;
    const int n0  = blockIdx.y * 64;

    float acc[8][4];
    #pragma unroll
    for (int i = 0; i < 8; i++)
        #pragma unroll
        for (int j = 0; j < 4; j++) acc[i][j] = 0.f;

    for (int k0 = 0; k0 < DIN; k0 += 16) {
        #pragma unroll
        for (int l = 0; l < 8; l++) {
            int idx = tid + l * 256;
            int m = idx >> 4, kk = idx & 15;
            int gm = m0 + m;
            As[kk][m] = (gm < NN) ? g_xa[(size_t)gm * DIN + k0 + kk] : 0.f;
        }
        #pragma unroll
        for (int l = 0; l < 4; l++) {
            int idx = tid + l * 256;
            int kk = idx >> 6, n = idx & 63;
            Bs[kk][n] = B[(size_t)(k0 + kk) * DH + n0 + n];
        }
        __syncthreads();
        #pragma unroll
        for (int kk = 0; kk < 16; kk++) {
            float a[8], b[4];
            #pragma unroll
            for (int i = 0; i < 8; i++) a[i] = As[kk][tr * 8 + i];
            #pragma unroll
            for (int j = 0; j < 4; j++) b[j] = Bs[kk][tc * 4 + j];
            #pragma unroll
            for (int i = 0; i < 8; i++)
                #pragma unroll
                for (int j = 0; j < 4; j++)
                    acc[i][j] = fmaf(a[i], b[j], acc[i][j]);
        }
        __syncthreads();
    }

    float4 bb = *(const float4*)(bias + n0 + tc * 4);
    #pragma unroll
    for (int i = 0; i < 8; i++) {
        int gm = m0 + tr * 8 + i;
        if (gm < NN) {
            float4 v;
            v.x = fmaxf(acc[i][0] + bb.x, 0.f);
            v.y = fmaxf(acc[i][1] + bb.y, 0.f);
            v.z = fmaxf(acc[i][2] + bb.z, 0.f);
            v.w = fmaxf(acc[i][3] + bb.w, 0.f);
            *(float4*)&g_h1a[(size_t)gm * DH + n0 + tc * 4] = v;
        }
    }
}

// ---------------- GEMM2 (smem W2, 128 rows/block): g_h2 = g_h1a @ W2 ----------------

__global__ __launch_bounds__(256) void k_gemm2s(const float* __restrict__ W2) {
    __shared__ float Ws[DH * DOUT];   // 16 KB
    int tid = threadIdx.x;
    for (int l = tid; l < DH * DOUT; l += 256) Ws[l] = W2[l];
    __syncthreads();
    int grp = tid >> 4, lane = tid & 15;
    int row0 = blockIdx.x * 128 + grp * 8;
    #pragma unroll
    for (int r = 0; r < 8; r++) {
        int row = row0 + r;
        if (row >= NN) return;
        const float4* a = (const float4*)(g_h1a + (size_t)row * DH);
        float acc = 0.f;
        #pragma unroll 8
        for (int k4 = 0; k4 < DH / 4; k4++) {
            float4 v = a[k4];
            int kb = k4 * 4;
            acc = fmaf(v.x, Ws[(kb + 0) * DOUT + lane], acc);
            acc = fmaf(v.y, Ws[(kb + 1) * DOUT + lane], acc);
            acc = fmaf(v.z, Ws[(kb + 2) * DOUT + lane], acc);
            acc = fmaf(v.w, Ws[(kb + 3) * DOUT + lane], acc);
        }
        g_h2[(size_t)row * DOUT + lane] = acc;
    }
}

// ---------------- layer-2: fused CSR gather + bias + log_softmax ----------------

__global__ __launch_bounds__(256) void k_l2fused(const float* __restrict__ b2,
                                                 float* __restrict__ out) {
    int tid  = threadIdx.x;
    int grp  = tid >> 4, lane = tid & 15;
    int i    = blockIdx.x * 16 + grp;
    if (i >= NN) return;
    float di = g_dinv[i];
    float acc = g_h2[(size_t)i * DOUT + lane] * di * di;

    int e = g_rowoff[i], end = g_rowoff[i + 1];
    for (; e + 2 <= end; e += 2) {
        int s0 = g_src[e], s1 = g_src[e + 1];
        float w0 = g_dinv[s0] * di, w1 = g_dinv[s1] * di;
        acc += g_h2[(size_t)s0 * DOUT + lane] * w0
             + g_h2[(size_t)s1 * DOUT + lane] * w1;
    }
    if (e < end) {
        int s = g_src[e];
        acc += g_h2[(size_t)s * DOUT + lane] * (g_dinv[s] * di);
    }
    acc += b2[lane];

    float m = acc;
    #pragma unroll
    for (int off = 8; off; off >>= 1)
        m = fmaxf(m, __shfl_xor_sync(0xffffffffu, m, off, 16));
    float ssum = expf(acc - m);
    #pragma unroll
    for (int off = 8; off; off >>= 1)
        ssum += __shfl_xor_sync(0xffffffffu, ssum, off, 16);
    out[(size_t)i * DOUT + lane] = acc - m - logf(ssum);
}

// ---------------- launch ----------------

extern "C" void kernel_launch(void* const* d_in, const int* in_sizes, int n_in,
                              void* d_out, int out_size) {
    const float *x = 0, *W1 = 0, *b1 = 0, *W2 = 0, *b2 = 0;
    const int* ei = 0;
    int E = NE;
    for (int i = 0; i < n_in; i++) {
        int c = in_sizes[i];
        if      (c == NN * DIN)  x  = (const float*)d_in[i];
        else if (c == 2 * NE)  { ei = (const int*)d_in[i]; E = NE; }
        else if (c == DIN * DH)  W1 = (const float*)d_in[i];
        else if (c == DH)        b1 = (const float*)d_in[i];
        else if (c == DH * DOUT) W2 = (const float*)d_in[i];
        else if (c == DOUT)      b2 = (const float*)d_in[i];
    }
    if (!x)  x  = (const float*)d_in[0];
    if (!ei) { ei = (const int*)d_in[1]; E = in_sizes[1] / 2; }
    if (!W1) W1 = (const float*)d_in[2];
    if (!b1) b1 = (const float*)d_in[3];
    if (!W2) W2 = (const float*)d_in[4];
    if (!b2) b2 = (const float*)d_in[5];
    float* out = (float*)d_out;

    // graph build (CSR by destination) — parallel scan
    k_zero_deg<<<(NN + 255) / 256, 256>>>();
    k_count<<<(E + 255) / 256, 256>>>(ei, E);
    k_scan1<<<NBLK, 1024>>>();
    k_scan2<<<1, 64>>>();
    k_scan3<<<(NN + 255) / 256, 256>>>();
    k_scatter<<<(E + 255) / 256, 256>>>(ei, E);

    // layer 1: CSR gather aggregation, then fused tiled GEMM+bias+relu
    k_agg1<<<(NN * 32 + 255) / 256, 256>>>(x);
    dim3 g1((NN + 127) / 128, DH / 64);
    k_gemm1t<<<g1, 256>>>(W1, b1);

    // layer 2: smem GEMM, then fused gather + bias + log_softmax
    k_gemm2s<<<(NN + 127) / 128, 256>>>(W2);
    k_l2fused<<<(NN + 15) / 16, 256>>>(b2, out);
}

// round 16
// speedup vs baseline: 5.5172x; 1.2476x over previous
#include <cuda_runtime.h>
#include <cuda_bf16.h>
#include <math.h>
#include <stdint.h>

#define NN   50000
#define NE   800000
#define DIN  128
#define DH   256
#define DOUT 16
#define NBLK ((NN + 1023) / 1024)
#define MTILES ((NN + 127) / 128)        // 391
#define MPAD   (MTILES * 128)            // 50048

// smem layout for mma GEMM (row stride 272B = 136 bf16, conflict-free ldmatrix)
#define SA_HI 0
#define SA_LO 34816
#define SB_HI 69632
#define SB_LO 87040
#define SMTOT 104448

// ---- static scratch: ONLY referenced from device code ----
__device__ int   g_deg[NN];
__device__ int   g_loc[NN];
__device__ int   g_bsum[NBLK];
__device__ int   g_boff[NBLK];
__device__ int   g_rowoff[NN + 1];
__device__ int   g_cursor[NN];
__device__ int   g_src[NE];
__device__ float g_dinv[NN];
__device__ __nv_bfloat16 g_xbh[(size_t)MPAD * DIN];   // (A_hat x) hi, row-major
__device__ __nv_bfloat16 g_xbl[(size_t)MPAD * DIN];   // lo
__device__ __nv_bfloat16 g_wth[DH * DIN];             // W1^T hi: [n][k]
__device__ __nv_bfloat16 g_wtl[DH * DIN];             // W1^T lo
__device__ float g_h1a[(size_t)NN * DH];
__device__ float g_h2 [(size_t)NN * DOUT];

__device__ __forceinline__ uint32_t smem_u32(const void* p) {
    uint32_t a;
    asm("{ .reg .u64 t; cvta.to.shared.u64 t, %1; cvt.u32.u64 %0, t; }" : "=r"(a) : "l"(p));
    return a;
}
#define LDSM_X4(r, addr) \
    asm volatile("ldmatrix.sync.aligned.m8n8.x4.shared.b16 {%0,%1,%2,%3}, [%4];" \
        : "=r"((r)[0]), "=r"((r)[1]), "=r"((r)[2]), "=r"((r)[3]) : "r"(addr))
#define MMA_BF16(d, a, b0, b1) \
    asm volatile("mma.sync.aligned.m16n8k16.row.col.f32.bf16.bf16.f32 " \
        "{%0,%1,%2,%3}, {%4,%5,%6,%7}, {%8,%9}, {%0,%1,%2,%3};" \
        : "+f"((d)[0]), "+f"((d)[1]), "+f"((d)[2]), "+f"((d)[3]) \
        : "r"((a)[0]), "r"((a)[1]), "r"((a)[2]), "r"((a)[3]), "r"(b0), "r"(b1))

// ---------------- graph build ----------------

__global__ void k_zero_deg() {
    int i = blockIdx.x * blockDim.x + threadIdx.x;
    if (i < NN) g_deg[i] = 0;
}

__global__ void k_count(const int* __restrict__ ei, int E) {
    int e = blockIdx.x * blockDim.x + threadIdx.x;
    if (e < E) {
        int d = ei[E + e];
        if ((unsigned)d < (unsigned)NN) atomicAdd(&g_deg[d], 1);
    }
}

__global__ __launch_bounds__(1024) void k_scan1() {
    __shared__ int sh[1024];
    int tid = threadIdx.x;
    int i = blockIdx.x * 1024 + tid;
    int v = (i < NN) ? g_deg[i] : 0;
    sh[tid] = v;
    __syncthreads();
    #pragma unroll
    for (int off = 1; off < 1024; off <<= 1) {
        int t = (tid >= off) ? sh[tid - off] : 0;
        __syncthreads();
        sh[tid] += t;
        __syncthreads();
    }
    if (i < NN) g_loc[i] = sh[tid] - v;
    if (tid == 1023) g_bsum[blockIdx.x] = sh[1023];
}

__global__ void k_scan2() {
    int tid = threadIdx.x;
    __shared__ int sh[64];
    int v = (tid < NBLK) ? g_bsum[tid] : 0;
    sh[tid] = v;
    __syncthreads();
    #pragma unroll
    for (int off = 1; off < 64; off <<= 1) {
        int t = (tid >= off) ? sh[tid - off] : 0;
        __syncthreads();
        sh[tid] += t;
        __syncthreads();
    }
    if (tid < NBLK) g_boff[tid] = sh[tid] - v;
    if (tid == 63) g_rowoff[NN] = sh[63];
}

__global__ void k_scan3() {
    int i = blockIdx.x * blockDim.x + threadIdx.x;
    if (i < NN) {
        int o = g_loc[i] + g_boff[i >> 10];
        g_rowoff[i] = o;
        g_cursor[i] = o;
        g_dinv[i]   = rsqrtf((float)(g_deg[i] + 1));
    }
}

__global__ void k_scatter(const int* __restrict__ ei, int E) {
    int e = blockIdx.x * blockDim.x + threadIdx.x;
    if (e < E) {
        int s = ei[e], d = ei[E + e];
        if ((unsigned)s < (unsigned)NN && (unsigned)d < (unsigned)NN) {
            int pos = atomicAdd(&g_cursor[d], 1);
            g_src[pos] = s;
        }
    }
}

// ---------------- W1 -> bf16 hi/lo transposed [n][k] ----------------

__global__ void k_w1conv(const float* __restrict__ W1) {
    int idx = blockIdx.x * blockDim.x + threadIdx.x;   // 32768
    if (idx >= DIN * DH) return;
    int n = idx >> 7, k = idx & 127;
    float v = W1[(size_t)k * DH + n];
    __nv_bfloat16 h = __float2bfloat16_rn(v);
    g_wth[idx] = h;
    g_wtl[idx] = __float2bfloat16_rn(v - __bfloat162float(h));
}

// ---------------- layer-1 agg: CSR gather -> bf16 hi/lo rows ----------------

__global__ __launch_bounds__(256) void k_agg1(const float* __restrict__ x) {
    int i    = (blockIdx.x * 256 + threadIdx.x) >> 5;
    int lane = threadIdx.x & 31;
    if (i >= NN) return;
    float di = g_dinv[i];
    float4 v = ((const float4*)(x + (size_t)i * DIN))[lane];
    float ws = di * di;
    float4 acc = make_float4(v.x * ws, v.y * ws, v.z * ws, v.w * ws);

    int e = g_rowoff[i], end = g_rowoff[i + 1];
    for (; e + 4 <= end; e += 4) {
        int s0 = g_src[e],     s1 = g_src[e + 1];
        int s2 = g_src[e + 2], s3 = g_src[e + 3];
        float w0 = g_dinv[s0] * di, w1 = g_dinv[s1] * di;
        float w2 = g_dinv[s2] * di, w3 = g_dinv[s3] * di;
        float4 a = ((const float4*)(x + (size_t)s0 * DIN))[lane];
        float4 b = ((const float4*)(x + (size_t)s1 * DIN))[lane];
        float4 c = ((const float4*)(x + (size_t)s2 * DIN))[lane];
        float4 d = ((const float4*)(x + (size_t)s3 * DIN))[lane];
        acc.x += a.x * w0 + b.x * w1 + c.x * w2 + d.x * w3;
        acc.y += a.y * w0 + b.y * w1 + c.y * w2 + d.y * w3;
        acc.z += a.z * w0 + b.z * w1 + c.z * w2 + d.z * w3;
        acc.w += a.w * w0 + b.w * w1 + c.w * w2 + d.w * w3;
    }
    for (; e < end; e++) {
        int s = g_src[e];
        float w = g_dinv[s] * di;
        float4 a = ((const float4*)(x + (size_t)s * DIN))[lane];
        acc.x += a.x * w; acc.y += a.y * w; acc.z += a.z * w; acc.w += a.w * w;
    }

    float hx = __bfloat162float(__float2bfloat16_rn(acc.x));
    float hy = __bfloat162float(__float2bfloat16_rn(acc.y));
    float hz = __bfloat162float(__float2bfloat16_rn(acc.z));
    float hw = __bfloat162float(__float2bfloat16_rn(acc.w));
    __nv_bfloat162 h01 = __floats2bfloat162_rn(hx, hy);
    __nv_bfloat162 h23 = __floats2bfloat162_rn(hz, hw);
    __nv_bfloat162 l01 = __floats2bfloat162_rn(acc.x - hx, acc.y - hy);
    __nv_bfloat162 l23 = __floats2bfloat162_rn(acc.z - hz, acc.w - hw);

    uint2 hv = make_uint2(*(uint32_t*)&h01, *(uint32_t*)&h23);
    uint2 lv = make_uint2(*(uint32_t*)&l01, *(uint32_t*)&l23);
    ((uint2*)(g_xbh + (size_t)i * DIN))[lane] = hv;
    ((uint2*)(g_xbl + (size_t)i * DIN))[lane] = lv;
}

// ---------------- GEMM1 via mma.sync bf16x3: h1a = relu((A_hat x) W1 + b1) ----------------
// CTA: 128M x 64N x 128K; 8 warps (4x2), warp tile 32x32.

__global__ __launch_bounds__(256) void k_gemm1_mma(const float* __restrict__ bias) {
    extern __shared__ char smem[];
    const int tid = threadIdx.x;
    const int wid = tid >> 5, lane = tid & 31;
    const int m0 = blockIdx.x * 128;
    const int n0 = blockIdx.y * 64;
    const int wm = wid >> 1, wn = wid & 1;

    // stage tiles: rows padded to 272 bytes
    {
        const char* srcAh = (const char*)g_xbh + (size_t)m0 * 256;
        const char* srcAl = (const char*)g_xbl + (size_t)m0 * 256;
        #pragma unroll
        for (int l = 0; l < 8; l++) {
            int idx = tid + l * 256;           // 0..2047
            int r = idx >> 4, c = idx & 15;
            *(uint4*)(smem + SA_HI + r * 272 + c * 16) = *(const uint4*)(srcAh + r * 256 + c * 16);
            *(uint4*)(smem + SA_LO + r * 272 + c * 16) = *(const uint4*)(srcAl + r * 256 + c * 16);
        }
        const char* srcBh = (const char*)g_wth + (size_t)n0 * 256;
        const char* srcBl = (const char*)g_wtl + (size_t)n0 * 256;
        #pragma unroll
        for (int l = 0; l < 4; l++) {
            int idx = tid + l * 256;           // 0..1023
            int r = idx >> 4, c = idx & 15;
            *(uint4*)(smem + SB_HI + r * 272 + c * 16) = *(const uint4*)(srcBh + r * 256 + c * 16);
            *(uint4*)(smem + SB_LO + r * 272 + c * 16) = *(const uint4*)(srcBl + r * 256 + c * 16);
        }
    }
    __syncthreads();

    uint32_t sbase = smem_u32(smem);
    float acc[2][4][4];
    #pragma unroll
    for (int mi = 0; mi < 2; mi++)
        #pragma unroll
        for (int ni = 0; ni < 4; ni++)
            #pragma unroll
            for (int q = 0; q < 4; q++) acc[mi][ni][q] = 0.f;

    const int aRow     = lane & 15;
    const int aColByte = ((lane >> 4) << 3) * 2;
    const int bRow     = (lane & 7) + ((lane >> 4) << 3);
    const int bColByte = (((lane >> 3) & 1) << 3) * 2;

    #pragma unroll
    for (int pass = 0; pass < 3; pass++) {
        uint32_t Ab = sbase + (pass == 2 ? SA_LO : SA_HI);
        uint32_t Bb = sbase + (pass == 1 ? SB_LO : SB_HI);
        #pragma unroll
        for (int kk = 0; kk < 8; kk++) {
            int kByte = kk * 32;
            uint32_t a[2][4], b[2][4];
            #pragma unroll
            for (int mi = 0; mi < 2; mi++) {
                int row = wm * 32 + mi * 16 + aRow;
                LDSM_X4(a[mi], Ab + row * 272 + kByte + aColByte);
            }
            #pragma unroll
            for (int p = 0; p < 2; p++) {
                int row = wn * 32 + p * 16 + bRow;
                LDSM_X4(b[p], Bb + row * 272 + kByte + bColByte);
            }
            #pragma unroll
            for (int mi = 0; mi < 2; mi++)
                #pragma unroll
                for (int ni = 0; ni < 4; ni++)
                    MMA_BF16(acc[mi][ni], a[mi], b[ni >> 1][(ni & 1) * 2], b[ni >> 1][(ni & 1) * 2 + 1]);
        }
    }

    // epilogue: fragment-direct stores, fused bias+relu
    #pragma unroll
    for (int mi = 0; mi < 2; mi++)
        #pragma unroll
        for (int ni = 0; ni < 4; ni++) {
            int col = n0 + wn * 32 + ni * 8 + (lane & 3) * 2;
            float2 bb = *(const float2*)(bias + col);
            int r0 = m0 + wm * 32 + mi * 16 + (lane >> 2);
            if (r0 < NN) {
                float2 v = make_float2(fmaxf(acc[mi][ni][0] + bb.x, 0.f),
                                       fmaxf(acc[mi][ni][1] + bb.y, 0.f));
                *(float2*)&g_h1a[(size_t)r0 * DH + col] = v;
            }
            int r1 = r0 + 8;
            if (r1 < NN) {
                float2 v = make_float2(fmaxf(acc[mi][ni][2] + bb.x, 0.f),
                                       fmaxf(acc[mi][ni][3] + bb.y, 0.f));
                *(float2*)&g_h1a[(size_t)r1 * DH + col] = v;
            }
        }
}

// ---------------- GEMM2 (smem W2, 128 rows/block) ----------------

__global__ __launch_bounds__(256) void k_gemm2s(const float* __restrict__ W2) {
    __shared__ float Ws[DH * DOUT];
    int tid = threadIdx.x;
    for (int l = tid; l < DH * DOUT; l += 256) Ws[l] = W2[l];
    __syncthreads();
    int grp = tid >> 4, lane = tid & 15;
    int row0 = blockIdx.x * 128 + grp * 8;
    #pragma unroll
    for (int r = 0; r < 8; r++) {
        int row = row0 + r;
        if (row >= NN) return;
        const float4* a = (const float4*)(g_h1a + (size_t)row * DH);
        float acc = 0.f;
        #pragma unroll 8
        for (int k4 = 0; k4 < DH / 4; k4++) {
            float4 v = a[k4];
            int kb = k4 * 4;
            acc = fmaf(v.x, Ws[(kb + 0) * DOUT + lane], acc);
            acc = fmaf(v.y, Ws[(kb + 1) * DOUT + lane], acc);
            acc = fmaf(v.z, Ws[(kb + 2) * DOUT + lane], acc);
            acc = fmaf(v.w, Ws[(kb + 3) * DOUT + lane], acc);
        }
        g_h2[(size_t)row * DOUT + lane] = acc;
    }
}

// ---------------- layer-2: fused CSR gather + bias + log_softmax ----------------

__global__ __launch_bounds__(256) void k_l2fused(const float* __restrict__ b2,
                                                 float* __restrict__ out) {
    int tid  = threadIdx.x;
    int grp  = tid >> 4, lane = tid & 15;
    int i    = blockIdx.x * 16 + grp;
    if (i >= NN) return;
    float di = g_dinv[i];
    float acc = g_h2[(size_t)i * DOUT + lane] * di * di;

    int e = g_rowoff[i], end = g_rowoff[i + 1];
    for (; e + 2 <= end; e += 2) {
        int s0 = g_src[e], s1 = g_src[e + 1];
        float w0 = g_dinv[s0] * di, w1 = g_dinv[s1] * di;
        acc += g_h2[(size_t)s0 * DOUT + lane] * w0
             + g_h2[(size_t)s1 * DOUT + lane] * w1;
    }
    if (e < end) {
        int s = g_src[e];
        acc += g_h2[(size_t)s * DOUT + lane] * (g_dinv[s] * di);
    }
    acc += b2[lane];

    float m = acc;
    #pragma unroll
    for (int off = 8; off; off >>= 1)
        m = fmaxf(m, __shfl_xor_sync(0xffffffffu, m, off, 16));
    float ssum = expf(acc - m);
    #pragma unroll
    for (int off = 8; off; off >>= 1)
        ssum += __shfl_xor_sync(0xffffffffu, ssum, off, 16);
    out[(size_t)i * DOUT + lane] = acc - m - logf(ssum);
}

// ---------------- launch ----------------

extern "C" void kernel_launch(void* const* d_in, const int* in_sizes, int n_in,
                              void* d_out, int out_size) {
    const float *x = 0, *W1 = 0, *b1 = 0, *W2 = 0, *b2 = 0;
    const int* ei = 0;
    int E = NE;
    for (int i = 0; i < n_in; i++) {
        int c = in_sizes[i];
        if      (c == NN * DIN)  x  = (const float*)d_in[i];
        else if (c == 2 * NE)  { ei = (const int*)d_in[i]; E = NE; }
        else if (c == DIN * DH)  W1 = (const float*)d_in[i];
        else if (c == DH)        b1 = (const float*)d_in[i];
        else if (c == DH * DOUT) W2 = (const float*)d_in[i];
        else if (c == DOUT)      b2 = (const float*)d_in[i];
    }
    if (!x)  x  = (const float*)d_in[0];
    if (!ei) { ei = (const int*)d_in[1]; E = in_sizes[1] / 2; }
    if (!W1) W1 = (const float*)d_in[2];
    if (!b1) b1 = (const float*)d_in[3];
    if (!W2) W2 = (const float*)d_in[4];
    if (!b2) b2 = (const float*)d_in[5];
    float* out = (float*)d_out;

    cudaFuncSetAttribute(k_gemm1_mma, cudaFuncAttributeMaxDynamicSharedMemorySize, SMTOT);

    // graph build
    k_zero_deg<<<(NN + 255) / 256, 256>>>();
    k_count<<<(E + 255) / 256, 256>>>(ei, E);
    k_scan1<<<NBLK, 1024>>>();
    k_scan2<<<1, 64>>>();
    k_scan3<<<(NN + 255) / 256, 256>>>();
    k_scatter<<<(E + 255) / 256, 256>>>(ei, E);

    // layer 1
    k_w1conv<<<(DIN * DH + 255) / 256, 256>>>(W1);
    k_agg1<<<(NN * 32 + 255) / 256, 256>>>(x);
    k_gemm1_mma<<<dim3(MTILES, 4), 256, SMTOT>>>(b1);

    // layer 2
    k_gemm2s<<<(NN + 127) / 128, 256>>>(W2);
    k_l2fused<<<(NN + 15) / 16, 256>>>(b2, out);
}

// round 17
// speedup vs baseline: 7.2787x; 1.3193x over previous
#include <cuda_runtime.h>
#include <cuda_bf16.h>
#include <math.h>
#include <stdint.h>

#define NN   50000
#define NE   800000
#define DIN  128
#define DH   256
#define DOUT 16
#define NBLK ((NN + 1023) / 1024)
#define MTILES ((NN + 127) / 128)        // 391
#define MPAD   (MTILES * 128)            // 50048

// smem layout for mma GEMM (row stride 272B, conflict-free ldmatrix) + W2 slice
#define SA_HI 0
#define SA_LO 34816
#define SB_HI 69632
#define SB_LO 87040
#define SW2   104448
#define SMTOT (104448 + 64 * 17 * 4)     // 108,  + 4352

// ---- static scratch: ONLY referenced from device code ----
__device__ int   g_deg[NN];
__device__ int   g_loc[NN];
__device__ int   g_bsum[NBLK];
__device__ int   g_rowoff[NN + 1];
__device__ int   g_cursor[NN];
__device__ int   g_src[NE];
__device__ float g_dinv[NN];
__device__ __nv_bfloat16 g_xbh[(size_t)MPAD * DIN];   // (A_hat x) hi, row-major (pad rows stay 0)
__device__ __nv_bfloat16 g_xbl[(size_t)MPAD * DIN];   // lo
__device__ __nv_bfloat16 g_wth[DH * DIN];             // W1^T hi: [n][k]
__device__ __nv_bfloat16 g_wtl[DH * DIN];             // W1^T lo
__device__ float g_h2 [(size_t)NN * DOUT];            // h1a @ W2 (accumulated)

__device__ __forceinline__ uint32_t smem_u32(const void* p) {
    uint32_t a;
    asm("{ .reg .u64 t; cvta.to.shared.u64 t, %1; cvt.u32.u64 %0, t; }" : "=r"(a) : "l"(p));
    return a;
}
#define LDSM_X4(r, addr) \
    asm volatile("ldmatrix.sync.aligned.m8n8.x4.shared.b16 {%0,%1,%2,%3}, [%4];" \
        : "=r"((r)[0]), "=r"((r)[1]), "=r"((r)[2]), "=r"((r)[3]) : "r"(addr))
#define MMA_BF16(d, a, b0, b1) \
    asm volatile("mma.sync.aligned.m16n8k16.row.col.f32.bf16.bf16.f32 " \
        "{%0,%1,%2,%3}, {%4,%5,%6,%7}, {%8,%9}, {%0,%1,%2,%3};" \
        : "+f"((d)[0]), "+f"((d)[1]), "+f"((d)[2]), "+f"((d)[3]) \
        : "r"((a)[0]), "r"((a)[1]), "r"((a)[2]), "r"((a)[3]), "r"(b0), "r"(b1))

// ---------------- prep: zero deg + W1 -> bf16 hi/lo transposed [n][k] ----------------

__global__ void k_prep(const float* __restrict__ W1) {
    int idx = blockIdx.x * blockDim.x + threadIdx.x;
    if (idx < NN) g_deg[idx] = 0;
    if (idx < DIN * DH) {
        int n = idx >> 7, k = idx & 127;
        float v = W1[(size_t)k * DH + n];
        __nv_bfloat16 h = __float2bfloat16_rn(v);
        g_wth[idx] = h;
        g_wtl[idx] = __float2bfloat16_rn(v - __bfloat162float(h));
    }
}

__global__ void k_count(const int* __restrict__ ei, int E) {
    int e = blockIdx.x * blockDim.x + threadIdx.x;
    if (e < E) {
        int d = ei[E + e];
        if ((unsigned)d < (unsigned)NN) atomicAdd(&g_deg[d], 1);
    }
}

__global__ __launch_bounds__(1024) void k_scan1() {
    __shared__ int sh[1024];
    int tid = threadIdx.x;
    int i = blockIdx.x * 1024 + tid;
    int v = (i < NN) ? g_deg[i] : 0;
    sh[tid] = v;
    __syncthreads();
    #pragma unroll
    for (int off = 1; off < 1024; off <<= 1) {
        int t = (tid >= off) ? sh[tid - off] : 0;
        __syncthreads();
        sh[tid] += t;
        __syncthreads();
    }
    if (i < NN) g_loc[i] = sh[tid] - v;
    if (tid == 1023) g_bsum[blockIdx.x] = sh[1023];
}

// scan3: (a) redundant block-level scan of g_bsum, (b) rowoff/cursor/dinv, (c) zero g_h2
__global__ __launch_bounds__(256) void k_scan3() {
    __shared__ int sh[64];
    __shared__ int excl_s[64];
    int tid = threadIdx.x;
    int v64 = 0;
    if (tid < 64) {
        v64 = (tid < NBLK) ? g_bsum[tid] : 0;
        sh[tid] = v64;
    }
    __syncthreads();
    #pragma unroll
    for (int off = 1; off < 64; off <<= 1) {
        int t = (tid >= off && tid < 64) ? sh[tid - off] : 0;
        __syncthreads();
        if (tid < 64) sh[tid] += t;
        __syncthreads();
    }
    if (tid < 64) excl_s[tid] = sh[tid] - v64;
    __syncthreads();

    int i = blockIdx.x * 256 + tid;
    if (i < NN) {
        int o = g_loc[i] + excl_s[i >> 10];
        g_rowoff[i] = o;
        g_cursor[i] = o;
        g_dinv[i]   = rsqrtf((float)(g_deg[i] + 1));
        // zero h2 row (16 floats)
        float4 z = make_float4(0.f, 0.f, 0.f, 0.f);
        float4* h2r = (float4*)(g_h2 + (size_t)i * DOUT);
        h2r[0] = z; h2r[1] = z; h2r[2] = z; h2r[3] = z;
    }
    if (blockIdx.x == 0 && tid == 0) g_rowoff[NN] = sh[NBLK - 1];
}

__global__ void k_scatter(const int* __restrict__ ei, int E) {
    int e = blockIdx.x * blockDim.x + threadIdx.x;
    if (e < E) {
        int s = ei[e], d = ei[E + e];
        if ((unsigned)s < (unsigned)NN && (unsigned)d < (unsigned)NN) {
            int pos = atomicAdd(&g_cursor[d], 1);
            g_src[pos] = s;
        }
    }
}

// ---------------- layer-1 agg: CSR gather -> bf16 hi/lo rows ----------------

__global__ __launch_bounds__(256) void k_agg1(const float* __restrict__ x) {
    int i    = (blockIdx.x * 256 + threadIdx.x) >> 5;
    int lane = threadIdx.x & 31;
    if (i >= NN) return;
    float di = g_dinv[i];
    float4 v = ((const float4*)(x + (size_t)i * DIN))[lane];
    float ws = di * di;
    float4 acc = make_float4(v.x * ws, v.y * ws, v.z * ws, v.w * ws);

    int e = g_rowoff[i], end = g_rowoff[i + 1];
    for (; e + 4 <= end; e += 4) {
        int s0 = g_src[e],     s1 = g_src[e + 1];
        int s2 = g_src[e + 2], s3 = g_src[e + 3];
        float w0 = g_dinv[s0] * di, w1 = g_dinv[s1] * di;
        float w2 = g_dinv[s2] * di, w3 = g_dinv[s3] * di;
        float4 a = ((const float4*)(x + (size_t)s0 * DIN))[lane];
        float4 b = ((const float4*)(x + (size_t)s1 * DIN))[lane];
        float4 c = ((const float4*)(x + (size_t)s2 * DIN))[lane];
        float4 d = ((const float4*)(x + (size_t)s3 * DIN))[lane];
        acc.x += a.x * w0 + b.x * w1 + c.x * w2 + d.x * w3;
        acc.y += a.y * w0 + b.y * w1 + c.y * w2 + d.y * w3;
        acc.z += a.z * w0 + b.z * w1 + c.z * w2 + d.z * w3;
        acc.w += a.w * w0 + b.w * w1 + c.w * w2 + d.w * w3;
    }
    for (; e < end; e++) {
        int s = g_src[e];
        float w = g_dinv[s] * di;
        float4 a = ((const float4*)(x + (size_t)s * DIN))[lane];
        acc.x += a.x * w; acc.y += a.y * w; acc.z += a.z * w; acc.w += a.w * w;
    }

    float hx = __bfloat162float(__float2bfloat16_rn(acc.x));
    float hy = __bfloat162float(__float2bfloat16_rn(acc.y));
    float hz = __bfloat162float(__float2bfloat16_rn(acc.z));
    float hw = __bfloat162float(__float2bfloat16_rn(acc.w));
    __nv_bfloat162 h01 = __floats2bfloat162_rn(hx, hy);
    __nv_bfloat162 h23 = __floats2bfloat162_rn(hz, hw);
    __nv_bfloat162 l01 = __floats2bfloat162_rn(acc.x - hx, acc.y - hy);
    __nv_bfloat162 l23 = __floats2bfloat162_rn(acc.z - hz, acc.w - hw);

    ((uint2*)(g_xbh + (size_t)i * DIN))[lane] = make_uint2(*(uint32_t*)&h01, *(uint32_t*)&h23);
    ((uint2*)(g_xbl + (size_t)i * DIN))[lane] = make_uint2(*(uint32_t*)&l01, *(uint32_t*)&l23);
}

// ---------------- GEMM1 bf16x3 mma + FUSED bias/relu/GEMM2 epilogue ----------------
// CTA: 128M x 64N x 128K; 8 warps (4x2), warp tile 32x32.
// Epilogue: h2[row][0..15] += relu(h1[row][n0..n0+63]+b1) @ W2[n0..n0+63][0..15]

__global__ __launch_bounds__(256) void k_gemm1_mma(const float* __restrict__ bias,
                                                   const float* __restrict__ W2) {
    extern __shared__ char smem[];
    const int tid = threadIdx.x;
    const int wid = tid >> 5, lane = tid & 31;
    const int m0 = blockIdx.x * 128;
    const int n0 = blockIdx.y * 64;
    const int wm = wid >> 1, wn = wid & 1;
    float* W2s = (float*)(smem + SW2);   // [64][17] padded

    // stage A/B tiles (rows padded to 272B) + W2 slice
    {
        const char* srcAh = (const char*)g_xbh + (size_t)m0 * 256;
        const char* srcAl = (const char*)g_xbl + (size_t)m0 * 256;
        #pragma unroll
        for (int l = 0; l < 8; l++) {
            int idx = tid + l * 256;
            int r = idx >> 4, c = idx & 15;
            *(uint4*)(smem + SA_HI + r * 272 + c * 16) = *(const uint4*)(srcAh + r * 256 + c * 16);
            *(uint4*)(smem + SA_LO + r * 272 + c * 16) = *(const uint4*)(srcAl + r * 256 + c * 16);
        }
        const char* srcBh = (const char*)g_wth + (size_t)n0 * 256;
        const char* srcBl = (const char*)g_wtl + (size_t)n0 * 256;
        #pragma unroll
        for (int l = 0; l < 4; l++) {
            int idx = tid + l * 256;
            int r = idx >> 4, c = idx & 15;
            *(uint4*)(smem + SB_HI + r * 272 + c * 16) = *(const uint4*)(srcBh + r * 256 + c * 16);
            *(uint4*)(smem + SB_LO + r * 272 + c * 16) = *(const uint4*)(srcBl + r * 256 + c * 16);
        }
        #pragma unroll
        for (int l = 0; l < 4; l++) {               // 1024 floats of W2 slice
            int idx = tid + l * 256;
            int c = idx >> 4, o = idx & 15;
            W2s[c * 17 + o] = W2[(size_t)(n0 + c) * DOUT + o];
        }
    }
    __syncthreads();

    uint32_t sbase = smem_u32(smem);
    float acc[2][4][4];
    #pragma unroll
    for (int mi = 0; mi < 2; mi++)
        #pragma unroll
        for (int ni = 0; ni < 4; ni++)
            #pragma unroll
            for (int q = 0; q < 4; q++) acc[mi][ni][q] = 0.f;

    const int aRow     = lane & 15;
    const int aColByte = ((lane >> 4) << 3) * 2;
    const int bRow     = (lane & 7) + ((lane >> 4) << 3);
    const int bColByte = (((lane >> 3) & 1) << 3) * 2;

    #pragma unroll
    for (int pass = 0; pass < 3; pass++) {
        uint32_t Ab = sbase + (pass == 2 ? SA_LO : SA_HI);
        uint32_t Bb = sbase + (pass == 1 ? SB_LO : SB_HI);
        #pragma unroll
        for (int kk = 0; kk < 8; kk++) {
            int kByte = kk * 32;
            uint32_t a[2][4], b[2][4];
            #pragma unroll
            for (int mi = 0; mi < 2; mi++) {
                int row = wm * 32 + mi * 16 + aRow;
                LDSM_X4(a[mi], Ab + row * 272 + kByte + aColByte);
            }
            #pragma unroll
            for (int p = 0; p < 2; p++) {
                int row = wn * 32 + p * 16 + bRow;
                LDSM_X4(b[p], Bb + row * 272 + kByte + bColByte);
            }
            #pragma unroll
            for (int mi = 0; mi < 2; mi++)
                #pragma unroll
                for (int ni = 0; ni < 4; ni++)
                    MMA_BF16(acc[mi][ni], a[mi], b[ni >> 1][(ni & 1) * 2], b[ni >> 1][(ni & 1) * 2 + 1]);
        }
    }

    // bias + relu in registers
    #pragma unroll
    for (int ni = 0; ni < 4; ni++) {
        int col = n0 + wn * 32 + ni * 8 + (lane & 3) * 2;
        float2 bb = *(const float2*)(bias + col);
        #pragma unroll
        for (int mi = 0; mi < 2; mi++) {
            acc[mi][ni][0] = fmaxf(acc[mi][ni][0] + bb.x, 0.f);
            acc[mi][ni][1] = fmaxf(acc[mi][ni][1] + bb.y, 0.f);
            acc[mi][ni][2] = fmaxf(acc[mi][ni][2] + bb.x, 0.f);
            acc[mi][ni][3] = fmaxf(acc[mi][ni][3] + bb.y, 0.f);
        }
    }

    // fused GEMM2: per (mi,half) -> partial h2 row, quad butterfly, atomicAdd
    #pragma unroll
    for (int mi = 0; mi < 2; mi++) {
        #pragma unroll
        for (int half = 0; half < 2; half++) {
            float p[16];
            #pragma unroll
            for (int o = 0; o < 16; o++) p[o] = 0.f;
            #pragma unroll
            for (int ni = 0; ni < 4; ni++) {
                int c = wn * 32 + ni * 8 + (lane & 3) * 2;   // local col
                float v0 = acc[mi][ni][half * 2];
                float v1 = acc[mi][ni][half * 2 + 1];
                #pragma unroll
                for (int o = 0; o < 16; o++)
                    p[o] = fmaf(v0, W2s[c * 17 + o], fmaf(v1, W2s[(c + 1) * 17 + o], p[o]));
            }
            #pragma unroll
            for (int o = 0; o < 16; o++) {
                p[o] += __shfl_xor_sync(0xffffffffu, p[o], 1);
                p[o] += __shfl_xor_sync(0xffffffffu, p[o], 2);
            }
            int row = m0 + wm * 32 + mi * 16 + (lane >> 2) + half * 8;
            if (row < NN) {
                int ob = (lane & 3) * 4;
                float* dst = g_h2 + (size_t)row * DOUT + ob;
                atomicAdd(dst + 0, p[ob + 0]);
                atomicAdd(dst + 1, p[ob + 1]);
                atomicAdd(dst + 2, p[ob + 2]);
                atomicAdd(dst + 3, p[ob + 3]);
            }
        }
    }
}

// ---------------- layer-2: fused CSR gather + bias + log_softmax ----------------

__global__ __launch_bounds__(256) void k_l2fused(const float* __restrict__ b2,
                                                 float* __restrict__ out) {
    int tid  = threadIdx.x;
    int grp  = tid >> 4, lane = tid & 15;
    int i    = blockIdx.x * 16 + grp;
    if (i >= NN) return;
    float di = g_dinv[i];
    float acc = g_h2[(size_t)i * DOUT + lane] * di * di;

    int e = g_rowoff[i], end = g_rowoff[i + 1];
    for (; e + 4 <= end; e += 4) {
        int s0 = g_src[e],     s1 = g_src[e + 1];
        int s2 = g_src[e + 2], s3 = g_src[e + 3];
        float w0 = g_dinv[s0] * di, w1 = g_dinv[s1] * di;
        float w2 = g_dinv[s2] * di, w3 = g_dinv[s3] * di;
        acc += g_h2[(size_t)s0 * DOUT + lane] * w0
             + g_h2[(size_t)s1 * DOUT + lane] * w1
             + g_h2[(size_t)s2 * DOUT + lane] * w2
             + g_h2[(size_t)s3 * DOUT + lane] * w3;
    }
    for (; e < end; e++) {
        int s = g_src[e];
        acc += g_h2[(size_t)s * DOUT + lane] * (g_dinv[s] * di);
    }
    acc += b2[lane];

    float m = acc;
    #pragma unroll
    for (int off = 8; off; off >>= 1)
        m = fmaxf(m, __shfl_xor_sync(0xffffffffu, m, off, 16));
    float ssum = expf(acc - m);
    #pragma unroll
    for (int off = 8; off; off >>= 1)
        ssum += __shfl_xor_sync(0xffffffffu, ssum, off, 16);
    out[(size_t)i * DOUT + lane] = acc - m - logf(ssum);
}

// ---------------- launch ----------------

extern "C" void kernel_launch(void* const* d_in, const int* in_sizes, int n_in,
                              void* d_out, int out_size) {
    const float *x = 0, *W1 = 0, *b1 = 0, *W2 = 0, *b2 = 0;
    const int* ei = 0;
    int E = NE;
    for (int i = 0; i < n_in; i++) {
        int c = in_sizes[i];
        if      (c == NN * DIN)  x  = (const float*)d_in[i];
        else if (c == 2 * NE)  { ei = (const int*)d_in[i]; E = NE; }
        else if (c == DIN * DH)  W1 = (const float*)d_in[i];
        else if (c == DH)        b1 = (const float*)d_in[i];
        else if (c == DH * DOUT) W2 = (const float*)d_in[i];
        else if (c == DOUT)      b2 = (const float*)d_in[i];
    }
    if (!x)  x  = (const float*)d_in[0];
    if (!ei) { ei = (const int*)d_in[1]; E = in_sizes[1] / 2; }
    if (!W1) W1 = (const float*)d_in[2];
    if (!b1) b1 = (const float*)d_in[3];
    if (!W2) W2 = (const float*)d_in[4];
    if (!b2) b2 = (const float*)d_in[5];
    float* out = (float*)d_out;

    cudaFuncSetAttribute(k_gemm1_mma, cudaFuncAttributeMaxDynamicSharedMemorySize, SMTOT);

    // graph build
    k_prep<<<(NN + 255) / 256, 256>>>(W1);
    k_count<<<(E + 255) / 256, 256>>>(ei, E);
    k_scan1<<<NBLK, 1024>>>();
    k_scan3<<<(NN + 255) / 256, 256>>>();
    k_scatter<<<(E + 255) / 256, 256>>>(ei, E);

    // layer 1 + fused layer-2 transform
    k_agg1<<<(NN * 32 + 255) / 256, 256>>>(x);
    k_gemm1_mma<<<dim3(MTILES, 4), 256, SMTOT>>>(b1, W2);

    // layer-2 aggregation + softmax
    k_l2fused<<<(NN + 15) / 16, 256>>>(b2, out);
}